// round 14
// baseline (speedup 1.0000x reference)
#include <cuda_runtime.h>
#include <cuda_fp16.h>
#include <cstdint>

#define B_SZ  2
#define N_TOK 512
#define D     64
#define H     128
#define OUTD  64
#define NTILES 4096
#define PAIR_GRID 296

// ---------------------------------------------------------------------------
// Scratch (device globals)
// ---------------------------------------------------------------------------
__device__ float    g_xa[B_SZ * N_TOK * H];        // x @ W1[:D] + b1  (fp32)
__device__ float    g_xb[B_SZ * N_TOK * H];        // x @ W1[D:]       (fp32)
__device__ uint32_t g_W2t[H * H / 2];              // W2^T fp16, [n][k] (half2 words)
__device__ float    g_pooled_part[B_SZ * 32 * H];  // 32 contention slots per batch
__device__ float    g_M[H * H];                    // W3 @ V1 (fp32)
__device__ float    g_d[H];                        // N^2*(b3@V1) + c1
__device__ int      g_ticket;                      // pair-kernel work queue
__device__ int      g_arrive;                      // phase-0 barrier (tail resets)

__device__ __forceinline__ uint32_t smem_u32(const void* p) {
    uint32_t a;
    asm("{ .reg .u64 tmp; cvta.to.shared.u64 tmp, %1; cvt.u32.u64 %0, tmp; }"
        : "=r"(a) : "l"(p));
    return a;
}
__device__ __forceinline__ void ldmatrix_x4(uint32_t* r, uint32_t addr) {
    asm volatile("ldmatrix.sync.aligned.m8n8.x4.shared.b16 {%0,%1,%2,%3}, [%4];"
        : "=r"(r[0]), "=r"(r[1]), "=r"(r[2]), "=r"(r[3]) : "r"(addr));
}
__device__ __forceinline__ void mma_f16(float* c, const uint32_t* a,
                                        uint32_t b0, uint32_t b1) {
    asm volatile(
        "mma.sync.aligned.m16n8k16.row.col.f32.f16.f16.f32 "
        "{%0,%1,%2,%3}, {%4,%5,%6,%7}, {%8,%9}, {%0,%1,%2,%3};"
        : "+f"(c[0]), "+f"(c[1]), "+f"(c[2]), "+f"(c[3])
        : "r"(a[0]), "r"(a[1]), "r"(a[2]), "r"(a[3]), "r"(b0), "r"(b1));
}

// SMEM layout (bytes). Row stride for A/B tiles: 272B (256B data + 16B pad)
#define RSTRIDE  272u
#define OFF_A    0u
#define OFF_B    34816u     // 128*272
#define OFF_XA   69632u     // 8  rows x 128 f32 (phase 0: x-row scratch)
#define OFF_XB   73728u     // 16 rows x 128 f32
#define OFF_B2   81920u     // 128 f32
#define OFF_RED  82432u     // 8 x 32 f32
#define SMEM_BYTES 83456u

// ---------------------------------------------------------------------------
// Persistent pair kernel with integrated setup (phase 0) + device barrier.
// Phase 0 (all 296 CTAs):
//   - CTA0: reset ticket.  CTAs [0,32): zero pooled slots.
//   - CTAs [32,64): W2 -> W2^T fp16 into g_W2t.
//   - all: prep rows (xa/xb = x @ W1 halves, b1 folded), strided by CTA.
//   - all: g_M = W3 @ V1 (1 output/thread), g_d (first 128 global threads).
// Barrier (all CTAs resident: 2/SM x 148 SMs). Then ticket loop as before.
// ---------------------------------------------------------------------------
__global__ __launch_bounds__(256, 2) void pair_mma_kernel(
    const float* __restrict__ x,  const float* __restrict__ W1,
    const float* __restrict__ b1, const float* __restrict__ W2,
    const float* __restrict__ b2, const float* __restrict__ W3,
    const float* __restrict__ b3, const float* __restrict__ V1,
    const float* __restrict__ c1)
{
    extern __shared__ __align__(16) char smem[];
    const uint32_t S0 = smem_u32(smem);
    __shared__ int s_tile;

    const int t = threadIdx.x;
    const int lane = t & 31, w = t >> 5;
    const int wm = w >> 2, wn = w & 3;          // 2 x 4 warp grid
    const int blk = blockIdx.x;

    // ================= PHASE 0: setup =================
    if (blk == 0 && t == 0) g_ticket = 0;
    {   // zero pooled slots (CTAs 0..31)
        const int e = blk * 256 + t;
        if (e < B_SZ * 32 * H) g_pooled_part[e] = 0.f;
    }
    if (blk >= 32 && blk < 64) {   // conv W2 -> W2^T fp16 (8192 words)
        const int e = (blk - 32) * 256 + t;
        const int n = e >> 6, kk = e & 63;
        __half2 v = __floats2half2_rn(W2[(2 * kk) * H + n],
                                      W2[(2 * kk + 1) * H + n]);
        g_W2t[n * 64 + kk] = *(uint32_t*)&v;
    }
    // prep: rows strided over CTAs; 256 threads = 128 h x {xa, xb}
    {
        float* sxrow = (float*)(smem + OFF_XA);
        const int h = t & 127, which = t >> 7;
        const float* Wcol = W1 + (which ? (size_t)D * H : 0) + h;
        for (int row = blk; row < B_SZ * N_TOK; row += PAIR_GRID) {
            if (t < D) sxrow[t] = x[row * D + t];
            __syncthreads();
            float a0 = 0.f, a1 = 0.f, a2 = 0.f, a3 = 0.f;
#pragma unroll 4
            for (int d = 0; d < D; d += 4) {
                a0 = fmaf(sxrow[d],     Wcol[(d    ) * H], a0);
                a1 = fmaf(sxrow[d + 1], Wcol[(d + 1) * H], a1);
                a2 = fmaf(sxrow[d + 2], Wcol[(d + 2) * H], a2);
                a3 = fmaf(sxrow[d + 3], Wcol[(d + 3) * H], a3);
            }
            const float v = (a0 + a1) + (a2 + a3);
            if (which == 0) g_xa[row * H + h] = v + b1[h];
            else            g_xb[row * H + h] = v;
            __syncthreads();
        }
    }
    // mcomp: g_M[k][h] = sum_m W3[k][m] * V1[m][h]  (1 output/thread)
    {
        const int gtid = blk * 256 + t;
        if (gtid < H * H) {
            const int k = gtid >> 7, hh = gtid & 127;
            float s0 = 0.f, s1 = 0.f, s2 = 0.f, s3 = 0.f;
#pragma unroll 8
            for (int m = 0; m < H; m += 4) {
                s0 = fmaf(W3[k * H + m],     V1[(m    ) * H + hh], s0);
                s1 = fmaf(W3[k * H + m + 1], V1[(m + 1) * H + hh], s1);
                s2 = fmaf(W3[k * H + m + 2], V1[(m + 2) * H + hh], s2);
                s3 = fmaf(W3[k * H + m + 3], V1[(m + 3) * H + hh], s3);
            }
            g_M[gtid] = (s0 + s1) + (s2 + s3);
        }
        // dvec: g_d[h] = N^2*(b3@V1)[h] + c1[h]  (CTA 64, first 128 threads)
        if (blk == 64 && t < H) {
            float s0 = 0.f, s1 = 0.f, s2 = 0.f, s3 = 0.f;
#pragma unroll 8
            for (int m = 0; m < H; m += 4) {
                s0 = fmaf(b3[m],     V1[(m    ) * H + t], s0);
                s1 = fmaf(b3[m + 1], V1[(m + 1) * H + t], s1);
                s2 = fmaf(b3[m + 2], V1[(m + 2) * H + t], s2);
                s3 = fmaf(b3[m + 3], V1[(m + 3) * H + t], s3);
            }
            g_d[t] = 262144.0f * ((s0 + s1) + (s2 + s3)) + c1[t];
        }
    }
    // ---- device-wide barrier (all 296 CTAs resident) ----
    __syncthreads();
    if (t == 0) {
        __threadfence();
        atomicAdd(&g_arrive, 1);
        while (atomicAdd(&g_arrive, 0) < PAIR_GRID) { }
        __threadfence();
    }
    __syncthreads();

    // ================= PHASE 1: pair GEMM =================
    // stage W2^T (fp16) into padded smem rows -- once per CTA
    {
        uint32_t* dstW = (uint32_t*)(smem + OFF_B);
        const uint32_t* srcW = g_W2t;
#pragma unroll
        for (int it = 0; it < 32; ++it) {
            const int e = t + 256 * it;         // [0, 8192)
            dstW[(e >> 6) * 68 + (e & 63)] = srcW[e];
        }
        if (t < 128) ((float*)(smem + OFF_B2))[t] = b2[t];
    }

    const uint32_t aBase = S0 + OFF_A
        + (uint32_t)(wm * 64 + (lane & 15)) * RSTRIDE + (uint32_t)((lane >> 4) << 4);
    const uint32_t bBase = S0 + OFF_B
        + (uint32_t)(wn * 32 + ((lane & 7) | ((lane >> 4) << 3))) * RSTRIDE
        + (uint32_t)(((lane >> 3) & 1) << 4);

    while (true) {
        if (t == 0) s_tile = atomicAdd(&g_ticket, 1);
        __syncthreads();
        const int tile = s_tile;
        if (tile >= NTILES) break;

        const int b  = tile >> 11;
        const int r  = tile & 2047;
        const int i0 = (r >> 6) * 16;
        const int jx = r & 63;
        const int j0 = jx * 8;

        // ---- stage xa/xb rows (fp32) ----
        {
            const float4* xaG = (const float4*)(g_xa + (size_t)(b * N_TOK + j0) * H);
            const float4* xbG = (const float4*)(g_xb + (size_t)(b * N_TOK + i0) * H);
            float4* sxa = (float4*)(smem + OFF_XA);
            float4* sxb = (float4*)(smem + OFF_XB);
            sxa[t] = xaG[t];                                // 8*32 = 256 float4
            sxb[t] = xbG[t];
            sxb[t + 256] = xbG[t + 256];                    // 16*32 = 512 float4
        }
        __syncthreads();

        // ---- build A tile: row p = il*8+jl, A[p][k] = fp16(relu(xa+xb)) ----
        {
            const float* sxa = (const float*)(smem + OFF_XA);
            const float* sxb = (const float*)(smem + OFF_XB);
            uint32_t* sA = (uint32_t*)(smem + OFF_A);
#pragma unroll
            for (int it = 0; it < 32; ++it) {
                const int e = t + 256 * it;     // [0, 8192) half2 words
                const int row = e >> 6, q = e & 63;
                const int jl = row & 7, il = row >> 3;
                const float2 va = *(const float2*)&sxa[jl * H + 2 * q];
                const float2 vb = *(const float2*)&sxb[il * H + 2 * q];
                const __half2 h2 = __floats2half2_rn(fmaxf(va.x + vb.x, 0.f),
                                                     fmaxf(va.y + vb.y, 0.f));
                sA[row * 68 + q] = *(const uint32_t*)&h2;
            }
        }
        __syncthreads();

        // ---- main loop: 8 k-steps of m16n8k16 ----
        float acc[4][4][4];
#pragma unroll
        for (int a = 0; a < 4; ++a)
#pragma unroll
            for (int c = 0; c < 4; ++c)
#pragma unroll
                for (int rr = 0; rr < 4; ++rr) acc[a][c][rr] = 0.f;

#pragma unroll
        for (int ks = 0; ks < 8; ++ks) {
            const uint32_t kb = (uint32_t)ks * 32u;
            uint32_t a_frag[4][4], b_frag[2][4];
#pragma unroll
            for (int mb = 0; mb < 4; ++mb)
                ldmatrix_x4(a_frag[mb], aBase + (uint32_t)mb * (16u * RSTRIDE) + kb);
#pragma unroll
            for (int nb = 0; nb < 2; ++nb)
                ldmatrix_x4(b_frag[nb], bBase + (uint32_t)nb * (16u * RSTRIDE) + kb);
#pragma unroll
            for (int mb = 0; mb < 4; ++mb)
#pragma unroll
                for (int nb = 0; nb < 2; ++nb) {
                    mma_f16(acc[mb][nb * 2 + 0], a_frag[mb], b_frag[nb][0], b_frag[nb][1]);
                    mma_f16(acc[mb][nb * 2 + 1], a_frag[mb], b_frag[nb][2], b_frag[nb][3]);
                }
        }

        // ---- epilogue: relu(+b2), sum over 128 pairs ----
        const float* sb2 = (const float*)(smem + OFF_B2);
        float* red = (float*)(smem + OFF_RED);
#pragma unroll
        for (int n8 = 0; n8 < 4; ++n8) {
            const int colA = wn * 32 + n8 * 8 + (lane & 3) * 2;
            const float b2a = sb2[colA], b2b = sb2[colA + 1];
            float pa = 0.f, pb = 0.f;
#pragma unroll
            for (int mb = 0; mb < 4; ++mb) {
                const float* c = acc[mb][n8];
                pa += fmaxf(c[0] + b2a, 0.f) + fmaxf(c[2] + b2a, 0.f);
                pb += fmaxf(c[1] + b2b, 0.f) + fmaxf(c[3] + b2b, 0.f);
            }
#pragma unroll
            for (int s = 16; s >= 4; s >>= 1) {
                pa += __shfl_xor_sync(0xFFFFFFFFu, pa, s);
                pb += __shfl_xor_sync(0xFFFFFFFFu, pb, s);
            }
            if (lane < 4) {
                red[w * 32 + n8 * 8 + lane * 2]     = pa;
                red[w * 32 + n8 * 8 + lane * 2 + 1] = pb;
            }
        }
        __syncthreads();
        if (t < 128) {
            const int cl = t & 31, wnb = t >> 5;
            const float s = red[wnb * 32 + cl] + red[(4 + wnb) * 32 + cl];
            atomicAdd(&g_pooled_part[(b * 32 + (jx & 31)) * H + t], s);
        }
    }
}

// ---------------------------------------------------------------------------
// tail: o = relu(pooled @ M + d); out = o @ V2 + c2. grid=2, 1024 thr,
// k-split 8. Also resets g_arrive for the next graph replay.
// ---------------------------------------------------------------------------
__global__ __launch_bounds__(1024) void tail_kernel(const float* __restrict__ V2,
                                                    const float* __restrict__ c2,
                                                    float* __restrict__ out)
{
    __shared__ float sp[H];          // pooled
    __shared__ float so[H];          // o
    __shared__ float part[8][H];
    const int b = blockIdx.x;
    const int t = threadIdx.x;

    // stage pooled: sum the 32 contention slots
    if (t < H) {
        float s = 0.f;
#pragma unroll 8
        for (int sl = 0; sl < 32; ++sl) s += g_pooled_part[(b * 32 + sl) * H + t];
        sp[t] = s;
    }
    __syncthreads();

    // layer 1: o = relu(pooled @ M + d)     (8 k-slices x 128 outputs)
    {
        const int ks = t >> 7, h = t & 127;
        const int k0 = ks * 16;
        float s0 = 0.f, s1 = 0.f, s2 = 0.f, s3 = 0.f;
#pragma unroll
        for (int k = 0; k < 16; k += 4) {
            s0 = fmaf(sp[k0 + k],     g_M[(k0 + k) * H + h],     s0);
            s1 = fmaf(sp[k0 + k + 1], g_M[(k0 + k + 1) * H + h], s1);
            s2 = fmaf(sp[k0 + k + 2], g_M[(k0 + k + 2) * H + h], s2);
            s3 = fmaf(sp[k0 + k + 3], g_M[(k0 + k + 3) * H + h], s3);
        }
        part[ks][h] = (s0 + s1) + (s2 + s3);
    }
    __syncthreads();
    if (t < H) {
        float v = g_d[t];
#pragma unroll
        for (int ks = 0; ks < 8; ++ks) v += part[ks][t];
        so[t] = v > 0.f ? v : 0.f;
    }
    __syncthreads();

    // layer 2: out = o @ V2 + c2            (8 k-slices x 64 outputs)
    if (t < 512) {
        const int ks = t >> 6, o = t & 63;
        const int k0 = ks * 16;
        float s0 = 0.f, s1 = 0.f, s2 = 0.f, s3 = 0.f;
#pragma unroll
        for (int k = 0; k < 16; k += 4) {
            s0 = fmaf(so[k0 + k],     V2[(k0 + k) * OUTD + o],     s0);
            s1 = fmaf(so[k0 + k + 1], V2[(k0 + k + 1) * OUTD + o], s1);
            s2 = fmaf(so[k0 + k + 2], V2[(k0 + k + 2) * OUTD + o], s2);
            s3 = fmaf(so[k0 + k + 3], V2[(k0 + k + 3) * OUTD + o], s3);
        }
        part[ks][o] = (s0 + s1) + (s2 + s3);
    }
    __syncthreads();
    if (t < OUTD) {
        float v = c2[t];
#pragma unroll
        for (int ks = 0; ks < 8; ++ks) v += part[ks][t];
        out[b * OUTD + t] = v;
    }
    if (b == 0 && t == 0) g_arrive = 0;   // reset barrier for next replay
}

// ---------------------------------------------------------------------------
extern "C" void kernel_launch(void* const* d_in, const int* in_sizes, int n_in,
                              void* d_out, int out_size)
{
    const float* x  = (const float*)d_in[0];
    const float* W1 = (const float*)d_in[1];
    const float* b1 = (const float*)d_in[2];
    const float* W2 = (const float*)d_in[3];
    const float* b2 = (const float*)d_in[4];
    const float* W3 = (const float*)d_in[5];
    const float* b3 = (const float*)d_in[6];
    const float* V1 = (const float*)d_in[7];
    const float* c1 = (const float*)d_in[8];
    const float* V2 = (const float*)d_in[9];
    const float* c2 = (const float*)d_in[10];
    float* out = (float*)d_out;

    cudaFuncSetAttribute(pair_mma_kernel, cudaFuncAttributeMaxDynamicSharedMemorySize,
                         (int)SMEM_BYTES);
    pair_mma_kernel<<<PAIR_GRID, 256, SMEM_BYTES>>>(x, W1, b1, W2, b2, W3, b3, V1, c1);

    tail_kernel<<<B_SZ, 1024>>>(V2, c2, out);
}

// round 15
// speedup vs baseline: 1.1126x; 1.1126x over previous
#include <cuda_runtime.h>
#include <cuda_fp16.h>
#include <cstdint>

#define B_SZ  2
#define N_TOK 512
#define D     64
#define H     128
#define OUTD  64
#define NTILES 4096
#define PAIR_GRID 296

// ---------------------------------------------------------------------------
// Scratch (device globals)
// ---------------------------------------------------------------------------
__device__ uint32_t g_xa[B_SZ * N_TOK * H / 2];    // fp16x2: x @ W1[:D] + b1
__device__ uint32_t g_xb[B_SZ * N_TOK * H / 2];    // fp16x2: x @ W1[D:]
__device__ uint32_t g_W2t[H * H / 2];              // W2^T fp16, [n][k] (half2 words)
__device__ float    g_pooled_part[B_SZ * 32 * H];  // 32 contention slots per batch
__device__ float    g_M[H * H];                    // W3 @ V1 (fp32)
__device__ float    g_d[H];                        // N^2*(b3@V1) + c1
__device__ int      g_ticket;                      // pair-kernel work queue
__device__ int      g_finish;                      // last-CTA election (self-reset)
__device__ float    g_dummy;                       // keep warm-loads alive

__device__ __forceinline__ uint32_t smem_u32(const void* p) {
    uint32_t a;
    asm("{ .reg .u64 tmp; cvta.to.shared.u64 tmp, %1; cvt.u32.u64 %0, tmp; }"
        : "=r"(a) : "l"(p));
    return a;
}
__device__ __forceinline__ void ldmatrix_x4(uint32_t* r, uint32_t addr) {
    asm volatile("ldmatrix.sync.aligned.m8n8.x4.shared.b16 {%0,%1,%2,%3}, [%4];"
        : "=r"(r[0]), "=r"(r[1]), "=r"(r[2]), "=r"(r[3]) : "r"(addr));
}
__device__ __forceinline__ void mma_f16(float* c, const uint32_t* a,
                                        uint32_t b0, uint32_t b1) {
    asm volatile(
        "mma.sync.aligned.m16n8k16.row.col.f32.f16.f16.f32 "
        "{%0,%1,%2,%3}, {%4,%5,%6,%7}, {%8,%9}, {%0,%1,%2,%3};"
        : "+f"(c[0]), "+f"(c[1]), "+f"(c[2]), "+f"(c[3])
        : "r"(a[0]), "r"(a[1]), "r"(a[2]), "r"(a[3]), "r"(b0), "r"(b1));
}

// SMEM layout (bytes). Row stride for A/B tiles: 272B (256B data + 16B pad)
#define RSTRIDE  272u
#define OFF_A    0u
#define OFF_B    34816u     // 128*272
#define OFF_XA   69632u     // 8  rows x 64 half2 words (2KB)
#define OFF_XB   71680u     // 16 rows x 64 half2 words (4KB)
#define OFF_B2   75776u     // 128 f32
#define OFF_RED  76288u     // 8 x 32 f32
#define SMEM_BYTES 77312u

// ---------------------------------------------------------------------------
// Merged setup kernel (R9 structure). Block roles:
//   [0,128)   MCOMP: g_M[k][h] = sum_m W3[k][m] * V1[m][h]
//   128       DVEC : g_d[h] = N^2*(b3@V1)[h] + c1[h]; reset ticket
//   [129,257) CONV : W2 -> W2^T fp16; zero pooled slots
//   [257,265) WARM : touch V2 into L2
//   [265,777) PREP : xa/xb = x @ W1 halves (b1 folded), packed to fp16x2
// ---------------------------------------------------------------------------
__global__ __launch_bounds__(128) void setup_kernel(const float* __restrict__ x,
                                                    const float* __restrict__ W1,
                                                    const float* __restrict__ b1,
                                                    const float* __restrict__ W2,
                                                    const float* __restrict__ W3,
                                                    const float* __restrict__ b3,
                                                    const float* __restrict__ V1,
                                                    const float* __restrict__ c1,
                                                    const float* __restrict__ V2)
{
    __shared__ float sbuf[128];
    __shared__ float sv[4][128];
    const int blk = blockIdx.x;
    const int t = threadIdx.x;

    if (blk < 128) {                       // ---- MCOMP ----
        const int k = blk;
        sbuf[t] = W3[k * H + t];
        __syncthreads();
        float a0 = 0.f, a1 = 0.f, a2 = 0.f, a3 = 0.f;
        float a4 = 0.f, a5 = 0.f, a6 = 0.f, a7 = 0.f;
#pragma unroll 4
        for (int m = 0; m < H; m += 8) {
            a0 = fmaf(sbuf[m    ], V1[(m    ) * H + t], a0);
            a1 = fmaf(sbuf[m + 1], V1[(m + 1) * H + t], a1);
            a2 = fmaf(sbuf[m + 2], V1[(m + 2) * H + t], a2);
            a3 = fmaf(sbuf[m + 3], V1[(m + 3) * H + t], a3);
            a4 = fmaf(sbuf[m + 4], V1[(m + 4) * H + t], a4);
            a5 = fmaf(sbuf[m + 5], V1[(m + 5) * H + t], a5);
            a6 = fmaf(sbuf[m + 6], V1[(m + 6) * H + t], a6);
            a7 = fmaf(sbuf[m + 7], V1[(m + 7) * H + t], a7);
        }
        g_M[k * H + t] = ((a0 + a1) + (a2 + a3)) + ((a4 + a5) + (a6 + a7));
    } else if (blk == 128) {               // ---- DVEC ----
        sbuf[t] = b3[t];
        __syncthreads();
        float a0 = 0.f, a1 = 0.f, a2 = 0.f, a3 = 0.f;
#pragma unroll 8
        for (int m = 0; m < H; m += 4) {
            a0 = fmaf(sbuf[m    ], V1[(m    ) * H + t], a0);
            a1 = fmaf(sbuf[m + 1], V1[(m + 1) * H + t], a1);
            a2 = fmaf(sbuf[m + 2], V1[(m + 2) * H + t], a2);
            a3 = fmaf(sbuf[m + 3], V1[(m + 3) * H + t], a3);
        }
        g_d[t] = 262144.0f * ((a0 + a1) + (a2 + a3)) + c1[t];
        if (t == 0) g_ticket = 0;
    } else if (blk < 257) {                // ---- CONV ----
        const int n = blk - 129;
        if (t < 64) {
            const int kk = t;
            __half2 v = __floats2half2_rn(W2[(2 * kk) * H + n],
                                          W2[(2 * kk + 1) * H + n]);
            g_W2t[n * 64 + kk] = *(uint32_t*)&v;
        } else {
            g_pooled_part[n * 64 + (t - 64)] = 0.f;   // 128*64 = 8192 slots
        }
    } else if (blk < 265) {                // ---- WARM V2 ----
        const int e = (blk - 257) * 1024 + t * 8;
        float s = 0.f;
#pragma unroll
        for (int i = 0; i < 8; ++i) s += V2[e + i];
        if (s == 1.2345e30f) g_dummy = s;
    } else {                               // ---- PREP ----
        const int row0 = (blk - 265) * 2;
        if (t < 2 * D) sbuf[t] = x[row0 * D + t];
        __syncthreads();
        const int h = t;
        float a0 = 0.f, a1 = 0.f, b0 = 0.f, b1v = 0.f;
#pragma unroll 16
        for (int d = 0; d < D; ++d) {
            const float wa = W1[d * H + h];
            const float wb = W1[(D + d) * H + h];
            a0  = fmaf(sbuf[d],      wa, a0);
            a1  = fmaf(sbuf[64 + d], wa, a1);
            b0  = fmaf(sbuf[d],      wb, b0);
            b1v = fmaf(sbuf[64 + d], wb, b1v);
        }
        const float bb = b1[h];
        sv[0][h] = a0 + bb;
        sv[1][h] = a1 + bb;
        sv[2][h] = b0;
        sv[3][h] = b1v;
        __syncthreads();
        // pack fp16x2: 4 arrays x 64 words = 256 words, 2 per thread
#pragma unroll
        for (int e = t; e < 256; e += 128) {
            const int arr = e >> 6, kk = e & 63;
            const __half2 v = __floats2half2_rn(sv[arr][2 * kk], sv[arr][2 * kk + 1]);
            const uint32_t word = *(const uint32_t*)&v;
            if (arr == 0)      g_xa[(row0    ) * 64 + kk] = word;
            else if (arr == 1) g_xa[(row0 + 1) * 64 + kk] = word;
            else if (arr == 2) g_xb[(row0    ) * 64 + kk] = word;
            else               g_xb[(row0 + 1) * 64 + kk] = word;
        }
    }
}

// ---------------------------------------------------------------------------
// Persistent pair kernel: 296 CTAs, ticket queue over 4096 tiles.
// W2 staged ONCE per CTA; per tile: stage fp16 xa/xb (6KB), build A with
// HADD2/HMAX2, 8x m16n8k16 k-steps, epilogue relu(+b2)+pair-sum -> atomicAdd.
// Last-finishing CTA runs the tail inline (pooled -> M -> V2 -> out).
// ---------------------------------------------------------------------------
__global__ __launch_bounds__(256, 2) void pair_mma_kernel(
    const float* __restrict__ b2, const float* __restrict__ V2,
    const float* __restrict__ c2, float* __restrict__ out)
{
    extern __shared__ __align__(16) char smem[];
    const uint32_t S0 = smem_u32(smem);
    __shared__ int s_tile;
    __shared__ int s_last;

    const int t = threadIdx.x;
    const int lane = t & 31, w = t >> 5;
    const int wm = w >> 2, wn = w & 3;          // 2 x 4 warp grid

    // ---- stage W2^T (fp16) into padded smem rows -- once per CTA ----
    {
        uint32_t* dstW = (uint32_t*)(smem + OFF_B);
        const uint32_t* srcW = g_W2t;
#pragma unroll
        for (int it = 0; it < 32; ++it) {
            const int e = t + 256 * it;         // [0, 8192)
            dstW[(e >> 6) * 68 + (e & 63)] = srcW[e];
        }
        if (t < 128) ((float*)(smem + OFF_B2))[t] = b2[t];
    }

    const uint32_t aBase = S0 + OFF_A
        + (uint32_t)(wm * 64 + (lane & 15)) * RSTRIDE + (uint32_t)((lane >> 4) << 4);
    const uint32_t bBase = S0 + OFF_B
        + (uint32_t)(wn * 32 + ((lane & 7) | ((lane >> 4) << 3))) * RSTRIDE
        + (uint32_t)(((lane >> 3) & 1) << 4);

    while (true) {
        if (t == 0) s_tile = atomicAdd(&g_ticket, 1);
        __syncthreads();
        const int tile = s_tile;
        if (tile >= NTILES) break;

        const int b  = tile >> 11;
        const int r  = tile & 2047;
        const int i0 = (r >> 6) * 16;
        const int jx = r & 63;
        const int j0 = jx * 8;

        // ---- stage xa/xb rows (fp16x2 words) ----
        {
            const uint32_t* xaG = g_xa + (size_t)(b * N_TOK + j0) * 64;   // 512 w
            const uint32_t* xbG = g_xb + (size_t)(b * N_TOK + i0) * 64;   // 1024 w
            uint32_t* sxa = (uint32_t*)(smem + OFF_XA);
            uint32_t* sxb = (uint32_t*)(smem + OFF_XB);
            sxa[t] = xaG[t];
            sxa[t + 256] = xaG[t + 256];
#pragma unroll
            for (int e = 0; e < 4; ++e) sxb[t + 256 * e] = xbG[t + 256 * e];
        }
        __syncthreads();

        // ---- build A tile: row p = il*8+jl, A[p][k] = relu_h2(xa+xb) ----
        {
            const __half2* sxa = (const __half2*)(smem + OFF_XA);
            const __half2* sxb = (const __half2*)(smem + OFF_XB);
            uint32_t* sA = (uint32_t*)(smem + OFF_A);
            const __half2 z2 = __floats2half2_rn(0.f, 0.f);
#pragma unroll
            for (int it = 0; it < 32; ++it) {
                const int e = t + 256 * it;     // [0, 8192) half2 words
                const int row = e >> 6, q = e & 63;
                const int jl = row & 7, il = row >> 3;
                const __half2 s = __hmax2(__hadd2(sxa[jl * 64 + q],
                                                  sxb[il * 64 + q]), z2);
                sA[row * 68 + q] = *(const uint32_t*)&s;
            }
        }
        __syncthreads();

        // ---- main loop: 8 k-steps of m16n8k16 ----
        float acc[4][4][4];
#pragma unroll
        for (int a = 0; a < 4; ++a)
#pragma unroll
            for (int c = 0; c < 4; ++c)
#pragma unroll
                for (int rr = 0; rr < 4; ++rr) acc[a][c][rr] = 0.f;

#pragma unroll
        for (int ks = 0; ks < 8; ++ks) {
            const uint32_t kb = (uint32_t)ks * 32u;
            uint32_t a_frag[4][4], b_frag[2][4];
#pragma unroll
            for (int mb = 0; mb < 4; ++mb)
                ldmatrix_x4(a_frag[mb], aBase + (uint32_t)mb * (16u * RSTRIDE) + kb);
#pragma unroll
            for (int nb = 0; nb < 2; ++nb)
                ldmatrix_x4(b_frag[nb], bBase + (uint32_t)nb * (16u * RSTRIDE) + kb);
#pragma unroll
            for (int mb = 0; mb < 4; ++mb)
#pragma unroll
                for (int nb = 0; nb < 2; ++nb) {
                    mma_f16(acc[mb][nb * 2 + 0], a_frag[mb], b_frag[nb][0], b_frag[nb][1]);
                    mma_f16(acc[mb][nb * 2 + 1], a_frag[mb], b_frag[nb][2], b_frag[nb][3]);
                }
        }

        // ---- epilogue: relu(+b2), sum over 128 pairs ----
        const float* sb2 = (const float*)(smem + OFF_B2);
        float* red = (float*)(smem + OFF_RED);
#pragma unroll
        for (int n8 = 0; n8 < 4; ++n8) {
            const int colA = wn * 32 + n8 * 8 + (lane & 3) * 2;
            const float b2a = sb2[colA], b2b = sb2[colA + 1];
            float pa = 0.f, pb = 0.f;
#pragma unroll
            for (int mb = 0; mb < 4; ++mb) {
                const float* c = acc[mb][n8];
                pa += fmaxf(c[0] + b2a, 0.f) + fmaxf(c[2] + b2a, 0.f);
                pb += fmaxf(c[1] + b2b, 0.f) + fmaxf(c[3] + b2b, 0.f);
            }
#pragma unroll
            for (int s = 16; s >= 4; s >>= 1) {
                pa += __shfl_xor_sync(0xFFFFFFFFu, pa, s);
                pb += __shfl_xor_sync(0xFFFFFFFFu, pb, s);
            }
            if (lane < 4) {
                red[w * 32 + n8 * 8 + lane * 2]     = pa;
                red[w * 32 + n8 * 8 + lane * 2 + 1] = pb;
            }
        }
        __syncthreads();
        if (t < 128) {
            const int cl = t & 31, wnb = t >> 5;
            const float s = red[wnb * 32 + cl] + red[(4 + wnb) * 32 + cl];
            atomicAdd(&g_pooled_part[(b * 32 + (jx & 31)) * H + t], s);
        }
        __syncthreads();
    }

    // ================= inline tail: last CTA only =================
    __threadfence();
    if (t == 0) s_last = (atomicAdd(&g_finish, 1) == PAIR_GRID - 1);
    __syncthreads();
    if (!s_last) return;
    __threadfence();

    float* sp = (float*)(smem + OFF_XA);   // 256 floats: pooled[b][h]
    float* so = (float*)(smem + OFF_XB);   // 256 floats: o[b][h]
    const int bb = t >> 7, h = t & 127;

    // pooled: sum the 32 contention slots
    {
        float s = 0.f;
#pragma unroll 8
        for (int sl = 0; sl < 32; ++sl) s += g_pooled_part[(bb * 32 + sl) * H + h];
        sp[t] = s;
    }
    __syncthreads();

    // layer 1: o = relu(pooled @ M + d)
    {
        float a0 = 0.f, a1 = 0.f, a2 = 0.f, a3 = 0.f;
        const float* pv = sp + bb * 128;
#pragma unroll 8
        for (int k = 0; k < H; k += 4) {
            a0 = fmaf(pv[k],     g_M[(k    ) * H + h], a0);
            a1 = fmaf(pv[k + 1], g_M[(k + 1) * H + h], a1);
            a2 = fmaf(pv[k + 2], g_M[(k + 2) * H + h], a2);
            a3 = fmaf(pv[k + 3], g_M[(k + 3) * H + h], a3);
        }
        const float v = (a0 + a1) + (a2 + a3) + g_d[h];
        so[t] = v > 0.f ? v : 0.f;
    }
    __syncthreads();

    // layer 2: out = o @ V2 + c2  (128 threads: 2 batches x 64 outputs)
    if (t < 128) {
        const int b2i = t >> 6, o = t & 63;
        const float* ov = so + b2i * 128;
        float a0 = c2[o], a1 = 0.f, a2 = 0.f, a3 = 0.f;
#pragma unroll 8
        for (int k = 0; k < H; k += 4) {
            a0 = fmaf(ov[k],     V2[(k    ) * OUTD + o], a0);
            a1 = fmaf(ov[k + 1], V2[(k + 1) * OUTD + o], a1);
            a2 = fmaf(ov[k + 2], V2[(k + 2) * OUTD + o], a2);
            a3 = fmaf(ov[k + 3], V2[(k + 3) * OUTD + o], a3);
        }
        out[b2i * OUTD + o] = (a0 + a1) + (a2 + a3);
    }
    __syncthreads();
    if (t == 0) g_finish = 0;              // reset for next graph replay
}

// ---------------------------------------------------------------------------
extern "C" void kernel_launch(void* const* d_in, const int* in_sizes, int n_in,
                              void* d_out, int out_size)
{
    const float* x  = (const float*)d_in[0];
    const float* W1 = (const float*)d_in[1];
    const float* b1 = (const float*)d_in[2];
    const float* W2 = (const float*)d_in[3];
    const float* b2 = (const float*)d_in[4];
    const float* W3 = (const float*)d_in[5];
    const float* b3 = (const float*)d_in[6];
    const float* V1 = (const float*)d_in[7];
    const float* c1 = (const float*)d_in[8];
    const float* V2 = (const float*)d_in[9];
    const float* c2 = (const float*)d_in[10];
    float* out = (float*)d_out;

    setup_kernel<<<777, 128>>>(x, W1, b1, W2, W3, b3, V1, c1, V2);

    cudaFuncSetAttribute(pair_mma_kernel, cudaFuncAttributeMaxDynamicSharedMemorySize,
                         (int)SMEM_BYTES);
    pair_mma_kernel<<<PAIR_GRID, 256, SMEM_BYTES>>>(b2, V2, c2, out);
}

// round 16
// speedup vs baseline: 1.3127x; 1.1799x over previous
#include <cuda_runtime.h>
#include <cuda_fp16.h>
#include <cstdint>

#define B_SZ  2
#define N_TOK 512
#define D     64
#define H     128
#define OUTD  64
#define NTILES 4096
#define PAIR_GRID 304

// ---------------------------------------------------------------------------
// Scratch (device globals)
// ---------------------------------------------------------------------------
__device__ uint4    g_xa[B_SZ * N_TOK * H / 8];    // fp16x2 words: x@W1[:D]+b1
__device__ uint4    g_xb[B_SZ * N_TOK * H / 8];    // fp16x2 words: x@W1[D:]
__device__ uint4    g_W2t[H * H / 8];              // W2^T fp16, [n][k]
__device__ float    g_pooled_part[B_SZ * 32 * H];  // 32 contention slots per batch
__device__ float    g_M[H * H];                    // W3 @ V1 (fp32)
__device__ float    g_d[H];                        // N^2*(b3@V1) + c1
__device__ int      g_ticket;                      // pair-kernel work queue
__device__ int      g_finish;                      // last-CTA election (self-reset)
__device__ float    g_dummy;                       // keep warm-loads alive

__device__ __forceinline__ uint32_t smem_u32(const void* p) {
    uint32_t a;
    asm("{ .reg .u64 tmp; cvta.to.shared.u64 tmp, %1; cvt.u32.u64 %0, tmp; }"
        : "=r"(a) : "l"(p));
    return a;
}
__device__ __forceinline__ void ldmatrix_x4(uint32_t* r, uint32_t addr) {
    asm volatile("ldmatrix.sync.aligned.m8n8.x4.shared.b16 {%0,%1,%2,%3}, [%4];"
        : "=r"(r[0]), "=r"(r[1]), "=r"(r[2]), "=r"(r[3]) : "r"(addr));
}
__device__ __forceinline__ void mma_f16(float* c, const uint32_t* a,
                                        uint32_t b0, uint32_t b1) {
    asm volatile(
        "mma.sync.aligned.m16n8k16.row.col.f32.f16.f16.f32 "
        "{%0,%1,%2,%3}, {%4,%5,%6,%7}, {%8,%9}, {%0,%1,%2,%3};"
        : "+f"(c[0]), "+f"(c[1]), "+f"(c[2]), "+f"(c[3])
        : "r"(a[0]), "r"(a[1]), "r"(a[2]), "r"(a[3]), "r"(b0), "r"(b1));
}

// SMEM layout (bytes). Row stride for A/B tiles: 272B (256B data + 16B pad)
#define RSTRIDE  272u
#define OFF_A    0u
#define OFF_B    34816u     // 128*272
#define OFF_XA   69632u     // 8  rows x 64 half2 words (2KB)
#define OFF_XB   71680u     // 16 rows x 64 half2 words (4KB)
#define OFF_B2   75776u     // 128 f32
#define OFF_RED  76288u     // 8 x 32 f32
#define SMEM_BYTES 77312u

// ---------------------------------------------------------------------------
// Merged setup kernel (R9 structure). Block roles:
//   [0,128)   MCOMP: g_M[k][h] = sum_m W3[k][m] * V1[m][h]
//   128       DVEC : g_d[h] = N^2*(b3@V1)[h] + c1[h]; reset ticket
//   [129,257) CONV : W2 -> W2^T fp16; zero pooled slots
//   [257,265) WARM : touch V2 into L2
//   [265,777) PREP : xa/xb = x @ W1 halves (b1 folded), packed to fp16x2
// ---------------------------------------------------------------------------
__global__ __launch_bounds__(128) void setup_kernel(const float* __restrict__ x,
                                                    const float* __restrict__ W1,
                                                    const float* __restrict__ b1,
                                                    const float* __restrict__ W2,
                                                    const float* __restrict__ W3,
                                                    const float* __restrict__ b3,
                                                    const float* __restrict__ V1,
                                                    const float* __restrict__ c1,
                                                    const float* __restrict__ V2)
{
    __shared__ float sbuf[128];
    __shared__ float sv[4][128];
    const int blk = blockIdx.x;
    const int t = threadIdx.x;

    if (blk < 128) {                       // ---- MCOMP ----
        const int k = blk;
        sbuf[t] = W3[k * H + t];
        __syncthreads();
        float a0 = 0.f, a1 = 0.f, a2 = 0.f, a3 = 0.f;
        float a4 = 0.f, a5 = 0.f, a6 = 0.f, a7 = 0.f;
#pragma unroll 4
        for (int m = 0; m < H; m += 8) {
            a0 = fmaf(sbuf[m    ], V1[(m    ) * H + t], a0);
            a1 = fmaf(sbuf[m + 1], V1[(m + 1) * H + t], a1);
            a2 = fmaf(sbuf[m + 2], V1[(m + 2) * H + t], a2);
            a3 = fmaf(sbuf[m + 3], V1[(m + 3) * H + t], a3);
            a4 = fmaf(sbuf[m + 4], V1[(m + 4) * H + t], a4);
            a5 = fmaf(sbuf[m + 5], V1[(m + 5) * H + t], a5);
            a6 = fmaf(sbuf[m + 6], V1[(m + 6) * H + t], a6);
            a7 = fmaf(sbuf[m + 7], V1[(m + 7) * H + t], a7);
        }
        g_M[k * H + t] = ((a0 + a1) + (a2 + a3)) + ((a4 + a5) + (a6 + a7));
    } else if (blk == 128) {               // ---- DVEC ----
        sbuf[t] = b3[t];
        __syncthreads();
        float a0 = 0.f, a1 = 0.f, a2 = 0.f, a3 = 0.f;
#pragma unroll 8
        for (int m = 0; m < H; m += 4) {
            a0 = fmaf(sbuf[m    ], V1[(m    ) * H + t], a0);
            a1 = fmaf(sbuf[m + 1], V1[(m + 1) * H + t], a1);
            a2 = fmaf(sbuf[m + 2], V1[(m + 2) * H + t], a2);
            a3 = fmaf(sbuf[m + 3], V1[(m + 3) * H + t], a3);
        }
        g_d[t] = 262144.0f * ((a0 + a1) + (a2 + a3)) + c1[t];
        if (t == 0) g_ticket = 0;
    } else if (blk < 257) {                // ---- CONV ----
        const int n = blk - 129;
        if (t < 64) {
            const int kk = t;
            __half2 v = __floats2half2_rn(W2[(2 * kk) * H + n],
                                          W2[(2 * kk + 1) * H + n]);
            ((uint32_t*)g_W2t)[n * 64 + kk] = *(uint32_t*)&v;
        } else {
            g_pooled_part[n * 64 + (t - 64)] = 0.f;   // 128*64 = 8192 slots
        }
    } else if (blk < 265) {                // ---- WARM V2 ----
        const int e = (blk - 257) * 1024 + t * 8;
        float s = 0.f;
#pragma unroll
        for (int i = 0; i < 8; ++i) s += V2[e + i];
        if (s == 1.2345e30f) g_dummy = s;
    } else {                               // ---- PREP ----
        const int row0 = (blk - 265) * 2;
        if (t < 2 * D) sbuf[t] = x[row0 * D + t];
        __syncthreads();
        const int h = t;
        float a0 = 0.f, a1 = 0.f, b0 = 0.f, b1v = 0.f;
#pragma unroll 16
        for (int d = 0; d < D; ++d) {
            const float wa = W1[d * H + h];
            const float wb = W1[(D + d) * H + h];
            a0  = fmaf(sbuf[d],      wa, a0);
            a1  = fmaf(sbuf[64 + d], wa, a1);
            b0  = fmaf(sbuf[d],      wb, b0);
            b1v = fmaf(sbuf[64 + d], wb, b1v);
        }
        const float bb = b1[h];
        sv[0][h] = a0 + bb;
        sv[1][h] = a1 + bb;
        sv[2][h] = b0;
        sv[3][h] = b1v;
        __syncthreads();
#pragma unroll
        for (int e = t; e < 256; e += 128) {
            const int arr = e >> 6, kk = e & 63;
            const __half2 v = __floats2half2_rn(sv[arr][2 * kk], sv[arr][2 * kk + 1]);
            const uint32_t word = *(const uint32_t*)&v;
            if (arr == 0)      ((uint32_t*)g_xa)[(row0    ) * 64 + kk] = word;
            else if (arr == 1) ((uint32_t*)g_xa)[(row0 + 1) * 64 + kk] = word;
            else if (arr == 2) ((uint32_t*)g_xb)[(row0    ) * 64 + kk] = word;
            else               ((uint32_t*)g_xb)[(row0 + 1) * 64 + kk] = word;
        }
    }
}

// ---------------------------------------------------------------------------
// Persistent pair kernel: 304 CTAs, ticket queue over 4096 tiles.
// Per tile: uint4 stage (6KB), uint4 HADD2/HMAX2 A-build, 8x m16n8k16,
// epilogue relu(+b2) accumulated in REGISTERS across tiles; flushed once per
// CTA (and on batch crossing). Last CTA runs tail inline. 3 syncs/tile.
// ---------------------------------------------------------------------------
__global__ __launch_bounds__(256, 2) void pair_mma_kernel(
    const float* __restrict__ b2, const float* __restrict__ V2,
    const float* __restrict__ c2, float* __restrict__ out)
{
    extern __shared__ __align__(16) char smem[];
    const uint32_t S0 = smem_u32(smem);
    __shared__ int s_tile;
    __shared__ int s_last;

    const int t = threadIdx.x;
    const int lane = t & 31, w = t >> 5;
    const int wm = w >> 2, wn = w & 3;          // 2 x 4 warp grid
    const int slot = blockIdx.x & 31;

    // ---- stage W2^T (fp16) into padded smem rows -- once per CTA ----
    {
        const uint4* srcW = g_W2t;
#pragma unroll
        for (int it = 0; it < 8; ++it) {
            const int e = t + 256 * it;         // [0, 2048) uint4
            const int row = e >> 4, q4 = e & 15;
            *(uint4*)(smem + OFF_B + row * RSTRIDE + q4 * 16) = srcW[e];
        }
        if (t < 128) ((float*)(smem + OFF_B2))[t] = b2[t];
    }

    const uint32_t aBase = S0 + OFF_A
        + (uint32_t)(wm * 64 + (lane & 15)) * RSTRIDE + (uint32_t)((lane >> 4) << 4);
    const uint32_t bBase = S0 + OFF_B
        + (uint32_t)(wn * 32 + ((lane & 7) | ((lane >> 4) << 3))) * RSTRIDE
        + (uint32_t)(((lane >> 3) & 1) << 4);

    float epi[8];
#pragma unroll
    for (int e = 0; e < 8; ++e) epi[e] = 0.f;
    int cur_b = 0;

    // flush epi -> pooled slots for batch fb (uniform across CTA)
    auto flush_epi = [&](int fb) {
        float* red = (float*)(smem + OFF_RED);
#pragma unroll
        for (int n8 = 0; n8 < 4; ++n8) {
            float pa = epi[2 * n8], pb = epi[2 * n8 + 1];
#pragma unroll
            for (int s = 16; s >= 4; s >>= 1) {
                pa += __shfl_xor_sync(0xFFFFFFFFu, pa, s);
                pb += __shfl_xor_sync(0xFFFFFFFFu, pb, s);
            }
            if (lane < 4) {
                red[w * 32 + n8 * 8 + lane * 2]     = pa;
                red[w * 32 + n8 * 8 + lane * 2 + 1] = pb;
            }
        }
        __syncthreads();
        if (t < 128) {
            const int cl = t & 31, wnb = t >> 5;
            atomicAdd(&g_pooled_part[(fb * 32 + slot) * H + t],
                      red[wnb * 32 + cl] + red[(4 + wnb) * 32 + cl]);
        }
        __syncthreads();
#pragma unroll
        for (int e = 0; e < 8; ++e) epi[e] = 0.f;
    };

    if (t == 0) s_tile = atomicAdd(&g_ticket, 1);
    __syncthreads();
    int tile = s_tile;

    while (tile < NTILES) {
        const int b  = tile >> 11;
        const int r  = tile & 2047;
        const int i0 = (r >> 6) * 16;
        const int j0 = (r & 63) * 8;
        if (b != cur_b) { flush_epi(cur_b); cur_b = b; }

        // ---- stage xa/xb rows (uint4) ----
        {
            const uint4* xaG = g_xa + (size_t)(b * N_TOK + j0) * 16;   // 128 u4
            const uint4* xbG = g_xb + (size_t)(b * N_TOK + i0) * 16;   // 256 u4
            if (t < 128) ((uint4*)(smem + OFF_XA))[t] = xaG[t];
            ((uint4*)(smem + OFF_XB))[t] = xbG[t];
        }
        __syncthreads();

        // ---- build A tile (uint4): row p = il*8+jl, A[p][k]=relu_h2(xa+xb) ----
        {
            const uint4* sxa = (const uint4*)(smem + OFF_XA);
            const uint4* sxb = (const uint4*)(smem + OFF_XB);
            const __half2 z2 = __floats2half2_rn(0.f, 0.f);
#pragma unroll
            for (int it = 0; it < 8; ++it) {
                const int e = t + 256 * it;     // [0, 2048) uint4
                const int row = e >> 4, q4 = e & 15;
                const int jl = row & 7, il = row >> 3;
                const uint4 va = sxa[jl * 16 + q4];
                const uint4 vb = sxb[il * 16 + q4];
                uint4 rr;
                {
                    __half2 h0 = __hmax2(__hadd2(*(const __half2*)&va.x,
                                                 *(const __half2*)&vb.x), z2);
                    __half2 h1 = __hmax2(__hadd2(*(const __half2*)&va.y,
                                                 *(const __half2*)&vb.y), z2);
                    __half2 h2 = __hmax2(__hadd2(*(const __half2*)&va.z,
                                                 *(const __half2*)&vb.z), z2);
                    __half2 h3 = __hmax2(__hadd2(*(const __half2*)&va.w,
                                                 *(const __half2*)&vb.w), z2);
                    rr.x = *(const uint32_t*)&h0;
                    rr.y = *(const uint32_t*)&h1;
                    rr.z = *(const uint32_t*)&h2;
                    rr.w = *(const uint32_t*)&h3;
                }
                *(uint4*)(smem + OFF_A + row * RSTRIDE + q4 * 16) = rr;
            }
        }
        __syncthreads();

        // ---- main loop: 8 k-steps of m16n8k16 ----
        float acc[4][4][4];
#pragma unroll
        for (int a = 0; a < 4; ++a)
#pragma unroll
            for (int c = 0; c < 4; ++c)
#pragma unroll
                for (int rr2 = 0; rr2 < 4; ++rr2) acc[a][c][rr2] = 0.f;

#pragma unroll
        for (int ks = 0; ks < 8; ++ks) {
            const uint32_t kb = (uint32_t)ks * 32u;
            uint32_t a_frag[4][4], b_frag[2][4];
#pragma unroll
            for (int mb = 0; mb < 4; ++mb)
                ldmatrix_x4(a_frag[mb], aBase + (uint32_t)mb * (16u * RSTRIDE) + kb);
#pragma unroll
            for (int nb = 0; nb < 2; ++nb)
                ldmatrix_x4(b_frag[nb], bBase + (uint32_t)nb * (16u * RSTRIDE) + kb);
#pragma unroll
            for (int mb = 0; mb < 4; ++mb)
#pragma unroll
                for (int nb = 0; nb < 2; ++nb) {
                    mma_f16(acc[mb][nb * 2 + 0], a_frag[mb], b_frag[nb][0], b_frag[nb][1]);
                    mma_f16(acc[mb][nb * 2 + 1], a_frag[mb], b_frag[nb][2], b_frag[nb][3]);
                }
        }

        // ---- epilogue: relu(+b2), accumulate in registers ----
        const float* sb2 = (const float*)(smem + OFF_B2);
#pragma unroll
        for (int n8 = 0; n8 < 4; ++n8) {
            const int colA = wn * 32 + n8 * 8 + (lane & 3) * 2;
            const float b2a = sb2[colA], b2b = sb2[colA + 1];
            float pa = 0.f, pb = 0.f;
#pragma unroll
            for (int mb = 0; mb < 4; ++mb) {
                const float* c = acc[mb][n8];
                pa += fmaxf(c[0] + b2a, 0.f) + fmaxf(c[2] + b2a, 0.f);
                pb += fmaxf(c[1] + b2b, 0.f) + fmaxf(c[3] + b2b, 0.f);
            }
            epi[2 * n8]     += pa;
            epi[2 * n8 + 1] += pb;
        }

        if (t == 0) s_tile = atomicAdd(&g_ticket, 1);
        __syncthreads();
        tile = s_tile;
    }
    flush_epi(cur_b);

    // ================= inline tail: last CTA only =================
    __threadfence();
    if (t == 0) s_last = (atomicAdd(&g_finish, 1) == PAIR_GRID - 1);
    __syncthreads();
    if (!s_last) return;
    __threadfence();

    float* sp = (float*)(smem + OFF_XA);   // 256 floats: pooled[b][h]
    float* so = (float*)(smem + OFF_XB);   // 256 floats: o[b][h]
    const int bb = t >> 7, h = t & 127;

    {   // pooled: sum the 32 contention slots
        float s = 0.f;
#pragma unroll 8
        for (int sl = 0; sl < 32; ++sl) s += g_pooled_part[(bb * 32 + sl) * H + h];
        sp[t] = s;
    }
    __syncthreads();

    {   // layer 1: o = relu(pooled @ M + d)
        float a0 = 0.f, a1 = 0.f, a2 = 0.f, a3 = 0.f;
        const float* pv = sp + bb * 128;
#pragma unroll 8
        for (int k = 0; k < H; k += 4) {
            a0 = fmaf(pv[k],     g_M[(k    ) * H + h], a0);
            a1 = fmaf(pv[k + 1], g_M[(k + 1) * H + h], a1);
            a2 = fmaf(pv[k + 2], g_M[(k + 2) * H + h], a2);
            a3 = fmaf(pv[k + 3], g_M[(k + 3) * H + h], a3);
        }
        const float v = (a0 + a1) + (a2 + a3) + g_d[h];
        so[t] = v > 0.f ? v : 0.f;
    }
    __syncthreads();

    // layer 2: out = o @ V2 + c2  (128 threads: 2 batches x 64 outputs)
    if (t < 128) {
        const int b2i = t >> 6, o = t & 63;
        const float* ov = so + b2i * 128;
        float a0 = c2[o], a1 = 0.f, a2 = 0.f, a3 = 0.f;
#pragma unroll 8
        for (int k = 0; k < H; k += 4) {
            a0 = fmaf(ov[k],     V2[(k    ) * OUTD + o], a0);
            a1 = fmaf(ov[k + 1], V2[(k + 1) * OUTD + o], a1);
            a2 = fmaf(ov[k + 2], V2[(k + 2) * OUTD + o], a2);
            a3 = fmaf(ov[k + 3], V2[(k + 3) * OUTD + o], a3);
        }
        out[b2i * OUTD + o] = (a0 + a1) + (a2 + a3);
    }
    __syncthreads();
    if (t == 0) g_finish = 0;              // reset for next graph replay
}

// ---------------------------------------------------------------------------
extern "C" void kernel_launch(void* const* d_in, const int* in_sizes, int n_in,
                              void* d_out, int out_size)
{
    const float* x  = (const float*)d_in[0];
    const float* W1 = (const float*)d_in[1];
    const float* b1 = (const float*)d_in[2];
    const float* W2 = (const float*)d_in[3];
    const float* b2 = (const float*)d_in[4];
    const float* W3 = (const float*)d_in[5];
    const float* b3 = (const float*)d_in[6];
    const float* V1 = (const float*)d_in[7];
    const float* c1 = (const float*)d_in[8];
    const float* V2 = (const float*)d_in[9];
    const float* c2 = (const float*)d_in[10];
    float* out = (float*)d_out;

    setup_kernel<<<777, 128>>>(x, W1, b1, W2, W3, b3, V1, c1, V2);

    cudaFuncSetAttribute(pair_mma_kernel, cudaFuncAttributeMaxDynamicSharedMemorySize,
                         (int)SMEM_BYTES);
    pair_mma_kernel<<<PAIR_GRID, 256, SMEM_BYTES>>>(b2, V2, c2, out);
}